// round 1
// baseline (speedup 1.0000x reference)
#include <cuda_runtime.h>
#include <cuda_bf16.h>
#include <math.h>

#define N_NODES 50000
#define E_EDGES 400000
#define E_TOT   (E_EDGES + N_NODES)   // +self loops = 450000
#define MAXC    256
#define BN_EPS  1e-5f
#define NEG_SLOPE 0.2f

// ---------------- device scratch (no allocations allowed) ----------------
__device__ float g_hfeat[N_NODES * MAXC];   // GEMM output (pre-aggregation features)
__device__ float g_bufA [N_NODES * MAXC];   // aggregation output (pre-BN)
__device__ float g_bufB [N_NODES * MAXC];   // BN+ReLU output (next layer input)
__device__ float g_ssrc [N_NODES * 4];
__device__ float g_sdst [N_NODES * 4];
__device__ int   g_deg     [N_NODES];
__device__ int   g_rowstart[N_NODES + 1];
__device__ int   g_cursor  [N_NODES];
__device__ int   g_csr_src [E_TOT];
__device__ float g_bnsum[512];              // [0:256) sum, [256:512) sumsq
__device__ float g_mu[MAXC], g_rstd[MAXC];

// ---------------- CSR construction (edge_index constant across layers) ----
__global__ void init_deg_kernel() {
    int i = blockIdx.x * blockDim.x + threadIdx.x;
    if (i < N_NODES) g_deg[i] = 0;
}

__global__ void count_deg_kernel(const int* __restrict__ ei) {
    int i = blockIdx.x * blockDim.x + threadIdx.x;
    if (i >= E_TOT) return;
    int d = (i < E_EDGES) ? ei[E_EDGES + i] : (i - E_EDGES);
    atomicAdd(&g_deg[d], 1);
}

// single-block exclusive scan over g_deg -> g_rowstart, g_cursor
__global__ void scan_kernel() {
    __shared__ int warp_sums[32];
    __shared__ int carry_s;
    int tid = threadIdx.x;
    int lane = tid & 31, wid = tid >> 5;
    if (tid == 0) carry_s = 0;
    __syncthreads();
    for (int base = 0; base < N_NODES; base += 1024) {
        int i = base + tid;
        int v = (i < N_NODES) ? g_deg[i] : 0;
        int x = v;
        #pragma unroll
        for (int d = 1; d < 32; d <<= 1) {
            int y = __shfl_up_sync(0xffffffffu, x, d);
            if (lane >= d) x += y;
        }
        if (lane == 31) warp_sums[wid] = x;
        __syncthreads();
        if (wid == 0) {
            int s = warp_sums[lane];
            #pragma unroll
            for (int d = 1; d < 32; d <<= 1) {
                int y = __shfl_up_sync(0xffffffffu, s, d);
                if (lane >= d) s += y;
            }
            warp_sums[lane] = s;
        }
        __syncthreads();
        int block_excl = (wid > 0) ? warp_sums[wid - 1] : 0;
        int incl = x + block_excl;
        int excl = incl - v;
        int c = carry_s;
        if (i < N_NODES) { g_rowstart[i] = c + excl; g_cursor[i] = c + excl; }
        __syncthreads();
        if (tid == 1023) carry_s = c + incl;
        __syncthreads();
    }
    if (tid == 0) g_rowstart[N_NODES] = carry_s;
}

__global__ void scatter_kernel(const int* __restrict__ ei) {
    int i = blockIdx.x * blockDim.x + threadIdx.x;
    if (i >= E_TOT) return;
    int s, d;
    if (i < E_EDGES) { s = ei[i]; d = ei[E_EDGES + i]; }
    else             { s = d = i - E_EDGES; }
    int pos = atomicAdd(&g_cursor[d], 1);
    g_csr_src[pos] = s;
}

// ---------------- SGEMM: C[M,N] = A[M,K] @ B[K,N], fp32 --------------------
// BM=128 BN=64 BK=16, 256 threads, 8x4 per-thread tile
__global__ void sgemm_kernel(const float* __restrict__ A, const float* __restrict__ B,
                             float* __restrict__ C, int M, int K, int N) {
    __shared__ float As[16][128];
    __shared__ float Bs[16][64];
    int t  = threadIdx.x;
    int m0 = blockIdx.x * 128;
    int n0 = blockIdx.y * 64;
    int ty = t >> 4, tx = t & 15;
    float acc[8][4];
    #pragma unroll
    for (int i = 0; i < 8; i++)
        #pragma unroll
        for (int j = 0; j < 4; j++) acc[i][j] = 0.f;

    int arow = t >> 2;          // 0..63
    int acol = (t & 3) * 4;     // 0,4,8,12
    int brow = t >> 4;          // 0..15
    int bcol = (t & 15) * 4;    // 0..60

    for (int k0 = 0; k0 < K; k0 += 16) {
        #pragma unroll
        for (int r = 0; r < 2; r++) {
            int gm = m0 + arow + r * 64;
            float4 v = (gm < M) ? *(const float4*)(A + (size_t)gm * K + k0 + acol)
                                : make_float4(0.f, 0.f, 0.f, 0.f);
            As[acol + 0][arow + r * 64] = v.x;
            As[acol + 1][arow + r * 64] = v.y;
            As[acol + 2][arow + r * 64] = v.z;
            As[acol + 3][arow + r * 64] = v.w;
        }
        *(float4*)&Bs[brow][bcol] = *(const float4*)(B + (size_t)(k0 + brow) * N + n0 + bcol);
        __syncthreads();
        #pragma unroll
        for (int k = 0; k < 16; k++) {
            float4 a01 = *(const float4*)&As[k][ty * 8];
            float4 a23 = *(const float4*)&As[k][ty * 8 + 4];
            float4 b   = *(const float4*)&Bs[k][tx * 4];
            float av[8] = {a01.x, a01.y, a01.z, a01.w, a23.x, a23.y, a23.z, a23.w};
            float bv[4] = {b.x, b.y, b.z, b.w};
            #pragma unroll
            for (int i = 0; i < 8; i++)
                #pragma unroll
                for (int j = 0; j < 4; j++)
                    acc[i][j] += av[i] * bv[j];
        }
        __syncthreads();
    }
    #pragma unroll
    for (int i = 0; i < 8; i++) {
        int gm = m0 + ty * 8 + i;
        if (gm < M) {
            float4 v = make_float4(acc[i][0], acc[i][1], acc[i][2], acc[i][3]);
            *(float4*)(C + (size_t)gm * N + n0 + tx * 4) = v;
        }
    }
}

// ---------------- per-(node,head) attention pre-dots ----------------------
template<int H, int C>
__global__ void s_compute_kernel(const float* __restrict__ asrc,
                                 const float* __restrict__ adst) {
    // zero BN accumulators for this layer (done here: runs before bn_stats)
    if (blockIdx.x == 0) {
        int tt = threadIdx.x;
        g_bnsum[tt] = 0.f;
        g_bnsum[tt + 256] = 0.f;
    }
    int p = blockIdx.x * 8 + (threadIdx.x >> 5);   // (node,head) pair index
    int lane = threadIdx.x & 31;
    if (p >= N_NODES * H) return;
    int n = p / H, h = p % H;
    const float* hp = g_hfeat + (size_t)n * (H * C) + h * C;
    float ss = 0.f, sd = 0.f;
    for (int c = lane; c < C; c += 32) {
        float v = hp[c];
        ss += v * asrc[h * C + c];
        sd += v * adst[h * C + c];
    }
    #pragma unroll
    for (int d = 16; d > 0; d >>= 1) {
        ss += __shfl_xor_sync(0xffffffffu, ss, d);
        sd += __shfl_xor_sync(0xffffffffu, sd, d);
    }
    if (lane == 0) { g_ssrc[n * H + h] = ss; g_sdst[n * H + h] = sd; }
}

// ---------------- segment-softmax aggregation: one warp per dst node ------
template<int H, int C>
__global__ void aggregate_kernel(const float* __restrict__ bias,
                                 float* __restrict__ out) {
    const int CH = H * C;
    int n = blockIdx.x * 4 + (threadIdx.x >> 5);
    if (n >= N_NODES) return;
    int lane = threadIdx.x & 31;
    int rs = g_rowstart[n], re = g_rowstart[n + 1];

    float sdst[H];
    #pragma unroll
    for (int h = 0; h < H; h++) sdst[h] = g_sdst[n * H + h];

    // pass 1: segment max
    float mx[H];
    #pragma unroll
    for (int h = 0; h < H; h++) mx[h] = -3.0e38f;
    for (int e = rs + lane; e < re; e += 32) {
        int s = g_csr_src[e];
        #pragma unroll
        for (int h = 0; h < H; h++) {
            float x = g_ssrc[s * H + h] + sdst[h];
            x = (x > 0.f) ? x : NEG_SLOPE * x;
            mx[h] = fmaxf(mx[h], x);
        }
    }
    #pragma unroll
    for (int h = 0; h < H; h++)
        #pragma unroll
        for (int d = 16; d > 0; d >>= 1)
            mx[h] = fmaxf(mx[h], __shfl_xor_sync(0xffffffffu, mx[h], d));

    // pass 2: denominator
    float dn[H];
    #pragma unroll
    for (int h = 0; h < H; h++) dn[h] = 0.f;
    for (int e = rs + lane; e < re; e += 32) {
        int s = g_csr_src[e];
        #pragma unroll
        for (int h = 0; h < H; h++) {
            float x = g_ssrc[s * H + h] + sdst[h];
            x = (x > 0.f) ? x : NEG_SLOPE * x;
            dn[h] += __expf(x - mx[h]);
        }
    }
    #pragma unroll
    for (int h = 0; h < H; h++)
        #pragma unroll
        for (int d = 16; d > 0; d >>= 1)
            dn[h] += __shfl_xor_sync(0xffffffffu, dn[h], d);

    // pass 3: weighted feature accumulation (divide by denom at the end)
    float acc[CH / 32];
    #pragma unroll
    for (int j = 0; j < CH / 32; j++) acc[j] = 0.f;
    for (int e = rs; e < re; e++) {
        int s = g_csr_src[e];
        float w[H];
        #pragma unroll
        for (int h = 0; h < H; h++) {
            float x = g_ssrc[s * H + h] + sdst[h];
            x = (x > 0.f) ? x : NEG_SLOPE * x;
            w[h] = __expf(x - mx[h]);
        }
        const float* hp = g_hfeat + (size_t)s * CH;
        #pragma unroll
        for (int j = 0; j < CH / 32; j++) {
            int c = lane + 32 * j;
            acc[j] += w[c / C] * hp[c];
        }
    }
    float* op = out + (size_t)n * CH;
    #pragma unroll
    for (int j = 0; j < CH / 32; j++) {
        int c = lane + 32 * j;
        op[c] = acc[j] / dn[c / C] + bias[c];
    }
}

// ---------------- BatchNorm ------------------------------------------------
__global__ void bn_stats_kernel(const float* __restrict__ in, int HC) {
    int c = threadIdx.x;
    int rows_per = (N_NODES + gridDim.x - 1) / gridDim.x;
    int r0 = blockIdx.x * rows_per;
    int r1 = min(r0 + rows_per, N_NODES);
    float s = 0.f, q = 0.f;
    for (int r = r0; r < r1; r++) {
        float v = in[(size_t)r * HC + c];
        s += v; q += v * v;
    }
    atomicAdd(&g_bnsum[c], s);
    atomicAdd(&g_bnsum[256 + c], q);
}

__global__ void bn_finalize_kernel() {
    int c = threadIdx.x;
    float mu  = g_bnsum[c] / (float)N_NODES;
    float var = g_bnsum[256 + c] / (float)N_NODES - mu * mu;
    g_mu[c]   = mu;
    g_rstd[c] = rsqrtf(var + BN_EPS);
}

__global__ void bn_apply_kernel(const float* __restrict__ in,
                                const float* __restrict__ gamma,
                                const float* __restrict__ beta,
                                float* __restrict__ out, int total, int HC) {
    int i = blockIdx.x * blockDim.x + threadIdx.x;
    if (i >= total) return;
    int c = i % HC;
    float y = gamma[c] * (in[i] - g_mu[c]) * g_rstd[c] + beta[c];
    out[i] = (y > 0.f) ? y : 0.f;
}

// ---------------- MLP head: warp per node ----------------------------------
__global__ void head_kernel(const float* __restrict__ hin,
                            const float* __restrict__ hw1, const float* __restrict__ hb1,
                            const float* __restrict__ hw2, const float* __restrict__ hb2,
                            float* __restrict__ out) {
    int n = blockIdx.x * 4 + (threadIdx.x >> 5);
    if (n >= N_NODES) return;
    int j = threadIdx.x & 31;                 // hidden unit 0..31
    const float* hp = hin + (size_t)n * 64;
    float hid = hb1[j];
    #pragma unroll
    for (int k = 0; k < 64; k++) hid += hp[k] * hw1[k * 32 + j];
    hid = (hid > 0.f) ? hid : 0.f;
    float o0 = hid * hw2[j * 2 + 0];
    float o1 = hid * hw2[j * 2 + 1];
    #pragma unroll
    for (int d = 16; d > 0; d >>= 1) {
        o0 += __shfl_xor_sync(0xffffffffu, o0, d);
        o1 += __shfl_xor_sync(0xffffffffu, o1, d);
    }
    if (j == 0) {
        out[n * 2 + 0] = o0 + hb2[0];
        out[n * 2 + 1] = o1 + hb2[1];
    }
}

// ---------------- host orchestration ---------------------------------------
extern "C" void kernel_launch(void* const* d_in, const int* in_sizes, int n_in,
                              void* d_out, int out_size) {
    const float* x  = (const float*)d_in[0];
    const int*   ei = (const int*)d_in[1];
    const float* hw1 = (const float*)d_in[26];
    const float* hb1 = (const float*)d_in[27];
    const float* hw2 = (const float*)d_in[28];
    const float* hb2 = (const float*)d_in[29];
    float* out = (float*)d_out;

    float *hfeat, *bufA, *bufB;
    cudaGetSymbolAddress((void**)&hfeat, g_hfeat);
    cudaGetSymbolAddress((void**)&bufA,  g_bufA);
    cudaGetSymbolAddress((void**)&bufB,  g_bufB);

    // CSR build (once; topology shared by all layers)
    init_deg_kernel<<<(N_NODES + 255) / 256, 256>>>();
    count_deg_kernel<<<(E_TOT + 255) / 256, 256>>>(ei);
    scan_kernel<<<1, 1024>>>();
    scatter_kernel<<<(E_TOT + 255) / 256, 256>>>(ei);

    const int Ks [4] = {128, 256, 256, 256};
    const int Hs [4] = {4, 4, 4, 1};
    const int HCs[4] = {256, 256, 256, 64};

    const float* in = x;
    for (int L = 0; L < 4; L++) {
        int base = 2 + L * 6;
        const float* W    = (const float*)d_in[base + 0];
        const float* asrc = (const float*)d_in[base + 1];
        const float* adst = (const float*)d_in[base + 2];
        const float* b    = (const float*)d_in[base + 3];
        const float* g    = (const float*)d_in[base + 4];
        const float* be   = (const float*)d_in[base + 5];
        int K = Ks[L], H = Hs[L], HC = HCs[L];

        dim3 gg((N_NODES + 127) / 128, HC / 64);
        sgemm_kernel<<<gg, 256>>>(in, W, hfeat, N_NODES, K, HC);

        int pairs = N_NODES * H;
        if (H == 4) {
            s_compute_kernel<4, 64><<<(pairs + 7) / 8, 256>>>(asrc, adst);
            aggregate_kernel<4, 64><<<(N_NODES + 3) / 4, 128>>>(b, bufA);
        } else {
            s_compute_kernel<1, 64><<<(pairs + 7) / 8, 256>>>(asrc, adst);
            aggregate_kernel<1, 64><<<(N_NODES + 3) / 4, 128>>>(b, bufA);
        }

        bn_stats_kernel<<<128, HC>>>(bufA, HC);
        bn_finalize_kernel<<<1, HC>>>();
        int total = N_NODES * HC;
        bn_apply_kernel<<<(total + 255) / 256, 256>>>(bufA, g, be, bufB, total, HC);

        in = bufB;
    }

    head_kernel<<<(N_NODES + 3) / 4, 128>>>(bufB, hw1, hb1, hw2, hb2, out);
}

// round 8
// speedup vs baseline: 1.1532x; 1.1532x over previous
#include <cuda_runtime.h>
#include <cuda_bf16.h>
#include <cstdint>
#include <math.h>

#define N_NODES 50000
#define E_EDGES 400000
#define E_TOT   (E_EDGES + N_NODES)
#define MAXC    256
#define BN_EPS  1e-5f
#define NEG_SLOPE 0.2f
#define M_PAD   50048          // 391 tiles of 128

// ---------------- device scratch ----------------
__device__ float g_hfeat[N_NODES * MAXC];
__device__ float g_bufA [N_NODES * MAXC];
__device__ float g_bufB [N_NODES * MAXC];
__device__ float g_ssrc [N_NODES * 4];
__device__ float g_sdst [N_NODES * 4];
__device__ int   g_deg     [N_NODES];
__device__ int   g_rowstart[N_NODES + 1];
__device__ int   g_cursor  [N_NODES];
__device__ int   g_csr_src [E_TOT];
__device__ float g_bnsum[512];
__device__ float g_mu[MAXC], g_rstd[MAXC];
// split-bf16 GEMM operands; rows >= N_NODES are never stored to output
__device__ uint16_t g_Abf[(size_t)M_PAD * 768];
__device__ uint16_t g_Bbf[256 * 768];

__device__ __forceinline__ uint16_t f2bf(float v) {
    return __bfloat16_as_ushort(__float2bfloat16(v));
}
__device__ __forceinline__ float bf2f(uint16_t u) {
    return __bfloat162float(__ushort_as_bfloat16(u));
}

#define MMA16816(d, a, b) \
    asm volatile("mma.sync.aligned.m16n8k16.row.col.f32.bf16.bf16.f32 " \
        "{%0,%1,%2,%3}, {%4,%5,%6,%7}, {%8,%9}, {%0,%1,%2,%3};" \
        : "+f"((d)[0]), "+f"((d)[1]), "+f"((d)[2]), "+f"((d)[3]) \
        : "r"((a)[0]), "r"((a)[1]), "r"((a)[2]), "r"((a)[3]), \
          "r"((b)[0]), "r"((b)[1]))

// ---------------- CSR construction ----------------
__global__ void init_deg_kernel() {
    int i = blockIdx.x * blockDim.x + threadIdx.x;
    if (i < N_NODES) g_deg[i] = 0;
}
__global__ void count_deg_kernel(const int* __restrict__ ei) {
    int i = blockIdx.x * blockDim.x + threadIdx.x;
    if (i >= E_TOT) return;
    int d = (i < E_EDGES) ? ei[E_EDGES + i] : (i - E_EDGES);
    atomicAdd(&g_deg[d], 1);
}
__global__ void scan_kernel() {
    __shared__ int warp_sums[32];
    __shared__ int carry_s;
    int tid = threadIdx.x;
    int lane = tid & 31, wid = tid >> 5;
    if (tid == 0) carry_s = 0;
    __syncthreads();
    for (int base = 0; base < N_NODES; base += 1024) {
        int i = base + tid;
        int v = (i < N_NODES) ? g_deg[i] : 0;
        int x = v;
        #pragma unroll
        for (int d = 1; d < 32; d <<= 1) {
            int y = __shfl_up_sync(0xffffffffu, x, d);
            if (lane >= d) x += y;
        }
        if (lane == 31) warp_sums[wid] = x;
        __syncthreads();
        if (wid == 0) {
            int s = warp_sums[lane];
            #pragma unroll
            for (int d = 1; d < 32; d <<= 1) {
                int y = __shfl_up_sync(0xffffffffu, s, d);
                if (lane >= d) s += y;
            }
            warp_sums[lane] = s;
        }
        __syncthreads();
        int block_excl = (wid > 0) ? warp_sums[wid - 1] : 0;
        int incl = x + block_excl;
        int excl = incl - v;
        int c = carry_s;
        if (i < N_NODES) { g_rowstart[i] = c + excl; g_cursor[i] = c + excl; }
        __syncthreads();
        if (tid == 1023) carry_s = c + incl;
        __syncthreads();
    }
    if (tid == 0) g_rowstart[N_NODES] = carry_s;
}
__global__ void scatter_kernel(const int* __restrict__ ei) {
    int i = blockIdx.x * blockDim.x + threadIdx.x;
    if (i >= E_TOT) return;
    int s, d;
    if (i < E_EDGES) { s = ei[i]; d = ei[E_EDGES + i]; }
    else             { s = d = i - E_EDGES; }
    int pos = atomicAdd(&g_cursor[d], 1);
    g_csr_src[pos] = s;
}

// ---------------- split-bf16 conversions ----------------
// layer 0 input: x [N,128] -> A' = [hi | hi | lo], row stride 384
__global__ void convertA0_kernel(const float* __restrict__ x) {
    int i = blockIdx.x * blockDim.x + threadIdx.x;
    if (i >= N_NODES * 128) return;
    int m = i >> 7, k = i & 127;
    float v = x[i];
    uint16_t hi = f2bf(v);
    uint16_t lo = f2bf(v - bf2f(hi));
    size_t r = (size_t)m * 384;
    g_Abf[r + k]       = hi;
    g_Abf[r + 128 + k] = hi;
    g_Abf[r + 256 + k] = lo;
}
// W [K,HC] -> B'[n,k'] = rows of W^T, segments [hi | lo | hi], row stride 3K
__global__ void convertB_kernel(const float* __restrict__ W, int K, int HC) {
    int i = blockIdx.x * blockDim.x + threadIdx.x;
    if (i >= K * HC) return;
    int k = i / HC, n = i % HC;
    float v = W[i];
    uint16_t hi = f2bf(v);
    uint16_t lo = f2bf(v - bf2f(hi));
    size_t r = (size_t)n * (3 * K);
    g_Bbf[r + k]         = hi;
    g_Bbf[r + K + k]     = lo;
    g_Bbf[r + 2 * K + k] = hi;
}

// ---------------- mma.sync bf16 GEMM: C = A'(M,K3) x B'(N,K3)^T ----------
// BM=128, BK=64, 256 threads = 8 warps (4x2), warp tile 32 x (BN/2)
template<int BN>
__global__ void __launch_bounds__(256)
gemm_mma_kernel(const uint16_t* __restrict__ A, const uint16_t* __restrict__ B,
                float* __restrict__ C, int M, int K3, int HC, int nchunks) {
    const int STRIDE = 72;                 // 64 + 8 pad (bf16 units)
    __shared__ uint16_t As[128 * STRIDE];  // 18 KB
    __shared__ uint16_t Bs[BN * STRIDE];

    int tid = threadIdx.x, wid = tid >> 5, lane = tid & 31;
    int g = lane >> 2, t = lane & 3;
    int m0 = blockIdx.x * 128;
    int n0 = blockIdx.y * BN;
    int warp_m = (wid & 3) * 32;
    int warp_n = (wid >> 2) * (BN / 2);
    const int NT = BN / 16;    // n-tiles per warp (8 or 4)
    const int BNL = BN / 32;   // B uint4 loads per thread (4 or 2)

    float acc[2][NT][4];
    #pragma unroll
    for (int i = 0; i < 2; i++)
        #pragma unroll
        for (int j = 0; j < NT; j++)
            #pragma unroll
            for (int q = 0; q < 4; q++) acc[i][j][q] = 0.f;

    uint4 pa[4], pb[BNL];
    const uint32_t* As32 = (const uint32_t*)As;
    const uint32_t* Bs32 = (const uint32_t*)Bs;

    // prefetch chunk 0
    #pragma unroll
    for (int i = 0; i < 4; i++) {
        int idx = i * 256 + tid, row = idx >> 3, c8 = idx & 7;
        pa[i] = *(const uint4*)(A + (size_t)(m0 + row) * K3 + c8 * 8);
    }
    #pragma unroll
    for (int i = 0; i < BNL; i++) {
        int idx = i * 256 + tid, row = idx >> 3, c8 = idx & 7;
        pb[i] = *(const uint4*)(B + (size_t)(n0 + row) * K3 + c8 * 8);
    }
    #pragma unroll
    for (int i = 0; i < 4; i++) {
        int idx = i * 256 + tid, row = idx >> 3, c8 = idx & 7;
        *(uint4*)(As + row * STRIDE + c8 * 8) = pa[i];
    }
    #pragma unroll
    for (int i = 0; i < BNL; i++) {
        int idx = i * 256 + tid, row = idx >> 3, c8 = idx & 7;
        *(uint4*)(Bs + row * STRIDE + c8 * 8) = pb[i];
    }
    __syncthreads();

    for (int c = 0; c < nchunks; c++) {
        // prefetch next chunk into registers
        if (c + 1 < nchunks) {
            int k0 = (c + 1) * 64;
            #pragma unroll
            for (int i = 0; i < 4; i++) {
                int idx = i * 256 + tid, row = idx >> 3, c8 = idx & 7;
                pa[i] = *(const uint4*)(A + (size_t)(m0 + row) * K3 + k0 + c8 * 8);
            }
            #pragma unroll
            for (int i = 0; i < BNL; i++) {
                int idx = i * 256 + tid, row = idx >> 3, c8 = idx & 7;
                pb[i] = *(const uint4*)(B + (size_t)(n0 + row) * K3 + k0 + c8 * 8);
            }
        }
        // compute on resident chunk: 4 k16 steps
        #pragma unroll
        for (int k16 = 0; k16 < 4; k16++) {
            uint32_t af[2][4];
            #pragma unroll
            for (int i = 0; i < 2; i++) {
                int r = warp_m + i * 16 + g;
                int base = r * 36 + k16 * 8 + t;         // 36 u32 per row
                af[i][0] = As32[base];
                af[i][1] = As32[base + 8 * 36];
                af[i][2] = As32[base + 4];
                af[i][3] = As32[base + 8 * 36 + 4];
            }
            #pragma unroll
            for (int j = 0; j < NT; j++) {
                uint32_t bf[2];
                int n = warp_n + j * 8 + g;
                int base = n * 36 + k16 * 8 + t;
                bf[0] = Bs32[base];
                bf[1] = Bs32[base + 4];
                MMA16816(acc[0][j], af[0], bf);
                MMA16816(acc[1][j], af[1], bf);
            }
        }
        __syncthreads();
        if (c + 1 < nchunks) {
            #pragma unroll
            for (int i = 0; i < 4; i++) {
                int idx = i * 256 + tid, row = idx >> 3, c8 = idx & 7;
                *(uint4*)(As + row * STRIDE + c8 * 8) = pa[i];
            }
            #pragma unroll
            for (int i = 0; i < BNL; i++) {
                int idx = i * 256 + tid, row = idx >> 3, c8 = idx & 7;
                *(uint4*)(Bs + row * STRIDE + c8 * 8) = pb[i];
            }
            __syncthreads();
        }
    }

    // epilogue
    #pragma unroll
    for (int i = 0; i < 2; i++) {
        int r0 = m0 + warp_m + i * 16 + g;
        #pragma unroll
        for (int j = 0; j < NT; j++) {
            int cc = n0 + warp_n + j * 8 + t * 2;
            if (r0 < M)
                *(float2*)(C + (size_t)r0 * HC + cc) = make_float2(acc[i][j][0], acc[i][j][1]);
            if (r0 + 8 < M)
                *(float2*)(C + (size_t)(r0 + 8) * HC + cc) = make_float2(acc[i][j][2], acc[i][j][3]);
        }
    }
}

// ---------------- attention pre-dots ----------------
template<int H, int C>
__global__ void s_compute_kernel(const float* __restrict__ asrc,
                                 const float* __restrict__ adst) {
    if (blockIdx.x == 0) {
        int tt = threadIdx.x;
        g_bnsum[tt] = 0.f;
        g_bnsum[tt + 256] = 0.f;
    }
    int p = blockIdx.x * 8 + (threadIdx.x >> 5);
    int lane = threadIdx.x & 31;
    if (p >= N_NODES * H) return;
    int n = p / H, h = p % H;
    const float* hp = g_hfeat + (size_t)n * (H * C) + h * C;
    float ss = 0.f, sd = 0.f;
    for (int c = lane; c < C; c += 32) {
        float v = hp[c];
        ss += v * asrc[h * C + c];
        sd += v * adst[h * C + c];
    }
    #pragma unroll
    for (int d = 16; d > 0; d >>= 1) {
        ss += __shfl_xor_sync(0xffffffffu, ss, d);
        sd += __shfl_xor_sync(0xffffffffu, sd, d);
    }
    if (lane == 0) { g_ssrc[n * H + h] = ss; g_sdst[n * H + h] = sd; }
}

// ---------------- segment-softmax aggregation ----------------
template<int H, int C>
__global__ void aggregate_kernel(const float* __restrict__ bias,
                                 float* __restrict__ out) {
    const int CH = H * C;
    int n = blockIdx.x * 4 + (threadIdx.x >> 5);
    if (n >= N_NODES) return;
    int lane = threadIdx.x & 31;
    int rs = g_rowstart[n], re = g_rowstart[n + 1];

    float sdst[H];
    #pragma unroll
    for (int h = 0; h < H; h++) sdst[h] = g_sdst[n * H + h];

    float mx[H];
    #pragma unroll
    for (int h = 0; h < H; h++) mx[h] = -3.0e38f;
    for (int e = rs + lane; e < re; e += 32) {
        int s = g_csr_src[e];
        #pragma unroll
        for (int h = 0; h < H; h++) {
            float x = g_ssrc[s * H + h] + sdst[h];
            x = (x > 0.f) ? x : NEG_SLOPE * x;
            mx[h] = fmaxf(mx[h], x);
        }
    }
    #pragma unroll
    for (int h = 0; h < H; h++)
        #pragma unroll
        for (int d = 16; d > 0; d >>= 1)
            mx[h] = fmaxf(mx[h], __shfl_xor_sync(0xffffffffu, mx[h], d));

    float dn[H];
    #pragma unroll
    for (int h = 0; h < H; h++) dn[h] = 0.f;
    for (int e = rs + lane; e < re; e += 32) {
        int s = g_csr_src[e];
        #pragma unroll
        for (int h = 0; h < H; h++) {
            float x = g_ssrc[s * H + h] + sdst[h];
            x = (x > 0.f) ? x : NEG_SLOPE * x;
            dn[h] += __expf(x - mx[h]);
        }
    }
    #pragma unroll
    for (int h = 0; h < H; h++)
        #pragma unroll
        for (int d = 16; d > 0; d >>= 1)
            dn[h] += __shfl_xor_sync(0xffffffffu, dn[h], d);

    float acc[CH / 32];
    #pragma unroll
    for (int j = 0; j < CH / 32; j++) acc[j] = 0.f;
    for (int e = rs; e < re; e++) {
        int s = g_csr_src[e];
        float w[H];
        #pragma unroll
        for (int h = 0; h < H; h++) {
            float x = g_ssrc[s * H + h] + sdst[h];
            x = (x > 0.f) ? x : NEG_SLOPE * x;
            w[h] = __expf(x - mx[h]);
        }
        const float* hp = g_hfeat + (size_t)s * CH;
        #pragma unroll
        for (int j = 0; j < CH / 32; j++) {
            int c = lane + 32 * j;
            acc[j] += w[c / C] * hp[c];
        }
    }
    float* op = out + (size_t)n * CH;
    #pragma unroll
    for (int j = 0; j < CH / 32; j++) {
        int c = lane + 32 * j;
        op[c] = acc[j] / dn[c / C] + bias[c];
    }
}

// ---------------- BatchNorm ----------------
__global__ void bn_stats_kernel(const float* __restrict__ in, int HC) {
    int c = threadIdx.x;
    int rows_per = (N_NODES + gridDim.x - 1) / gridDim.x;
    int r0 = blockIdx.x * rows_per;
    int r1 = min(r0 + rows_per, N_NODES);
    float s = 0.f, q = 0.f;
    for (int r = r0; r < r1; r++) {
        float v = in[(size_t)r * HC + c];
        s += v; q += v * v;
    }
    atomicAdd(&g_bnsum[c], s);
    atomicAdd(&g_bnsum[256 + c], q);
}
__global__ void bn_finalize_kernel() {
    int c = threadIdx.x;
    float mu  = g_bnsum[c] / (float)N_NODES;
    float var = g_bnsum[256 + c] / (float)N_NODES - mu * mu;
    g_mu[c]   = mu;
    g_rstd[c] = rsqrtf(var + BN_EPS);
}
// BN+ReLU; optionally also emits the split-bf16 A' for the next layer (K=256)
__global__ void bn_apply_kernel(const float* __restrict__ in,
                                const float* __restrict__ gamma,
                                const float* __restrict__ beta,
                                float* __restrict__ out, int total, int HC,
                                int write_split) {
    int i = blockIdx.x * blockDim.x + threadIdx.x;
    if (i >= total) return;
    int c = i % HC;
    float y = gamma[c] * (in[i] - g_mu[c]) * g_rstd[c] + beta[c];
    y = (y > 0.f) ? y : 0.f;
    out[i] = y;
    if (write_split) {
        int m = i / HC;
        uint16_t hi = f2bf(y);
        uint16_t lo = f2bf(y - bf2f(hi));
        size_t r = (size_t)m * 768;
        g_Abf[r + c]       = hi;
        g_Abf[r + 256 + c] = hi;
        g_Abf[r + 512 + c] = lo;
    }
}

// ---------------- MLP head ----------------
__global__ void head_kernel(const float* __restrict__ hin,
                            const float* __restrict__ hw1, const float* __restrict__ hb1,
                            const float* __restrict__ hw2, const float* __restrict__ hb2,
                            float* __restrict__ out) {
    int n = blockIdx.x * 4 + (threadIdx.x >> 5);
    if (n >= N_NODES) return;
    int j = threadIdx.x & 31;
    const float* hp = hin + (size_t)n * 64;
    float hid = hb1[j];
    #pragma unroll
    for (int k = 0; k < 64; k++) hid += hp[k] * hw1[k * 32 + j];
    hid = (hid > 0.f) ? hid : 0.f;
    float o0 = hid * hw2[j * 2 + 0];
    float o1 = hid * hw2[j * 2 + 1];
    #pragma unroll
    for (int d = 16; d > 0; d >>= 1) {
        o0 += __shfl_xor_sync(0xffffffffu, o0, d);
        o1 += __shfl_xor_sync(0xffffffffu, o1, d);
    }
    if (j == 0) {
        out[n * 2 + 0] = o0 + hb2[0];
        out[n * 2 + 1] = o1 + hb2[1];
    }
}

// ---------------- host orchestration ----------------
extern "C" void kernel_launch(void* const* d_in, const int* in_sizes, int n_in,
                              void* d_out, int out_size) {
    const float* x   = (const float*)d_in[0];
    const int*   ei  = (const int*)d_in[1];
    const float* hw1 = (const float*)d_in[26];
    const float* hb1 = (const float*)d_in[27];
    const float* hw2 = (const float*)d_in[28];
    const float* hb2 = (const float*)d_in[29];
    float* out = (float*)d_out;

    float *hfeat, *bufA, *bufB;
    uint16_t *Abf, *Bbf;
    cudaGetSymbolAddress((void**)&hfeat, g_hfeat);
    cudaGetSymbolAddress((void**)&bufA,  g_bufA);
    cudaGetSymbolAddress((void**)&bufB,  g_bufB);
    cudaGetSymbolAddress((void**)&Abf,   g_Abf);
    cudaGetSymbolAddress((void**)&Bbf,   g_Bbf);

    // CSR build (topology shared by all layers)
    init_deg_kernel<<<(N_NODES + 255) / 256, 256>>>();
    count_deg_kernel<<<(E_TOT + 255) / 256, 256>>>(ei);
    scan_kernel<<<1, 1024>>>();
    scatter_kernel<<<(E_TOT + 255) / 256, 256>>>(ei);

    // layer 0 A' conversion
    convertA0_kernel<<<(N_NODES * 128 + 255) / 256, 256>>>(x);

    const int Ks [4] = {128, 256, 256, 256};
    const int Hs [4] = {4, 4, 4, 1};
    const int HCs[4] = {256, 256, 256, 64};
    const int MT = M_PAD / 128;   // 391

    for (int L = 0; L < 4; L++) {
        int base = 2 + L * 6;
        const float* W    = (const float*)d_in[base + 0];
        const float* asrc = (const float*)d_in[base + 1];
        const float* adst = (const float*)d_in[base + 2];
        const float* b    = (const float*)d_in[base + 3];
        const float* g    = (const float*)d_in[base + 4];
        const float* be   = (const float*)d_in[base + 5];
        int K = Ks[L], H = Hs[L], HC = HCs[L];
        int K3 = 3 * K, nchunks = K3 / 64;

        convertB_kernel<<<(K * HC + 255) / 256, 256>>>(W, K, HC);

        if (HC == 256) {
            dim3 gg(MT, 2);
            gemm_mma_kernel<128><<<gg, 256>>>(Abf, Bbf, hfeat, N_NODES, K3, HC, nchunks);
        } else {
            dim3 gg(MT, 1);
            gemm_mma_kernel<64><<<gg, 256>>>(Abf, Bbf, hfeat, N_NODES, K3, HC, nchunks);
        }

        int pairs = N_NODES * H;
        if (H == 4) {
            s_compute_kernel<4, 64><<<(pairs + 7) / 8, 256>>>(asrc, adst);
            aggregate_kernel<4, 64><<<(N_NODES + 3) / 4, 128>>>(b, bufA);
        } else {
            s_compute_kernel<1, 64><<<(pairs + 7) / 8, 256>>>(asrc, adst);
            aggregate_kernel<1, 64><<<(N_NODES + 3) / 4, 128>>>(b, bufA);
        }

        bn_stats_kernel<<<128, HC>>>(bufA, HC);
        bn_finalize_kernel<<<1, HC>>>();
        int total = N_NODES * HC;
        bn_apply_kernel<<<(total + 255) / 256, 256>>>(bufA, g, be, bufB, total, HC,
                                                      (L < 3) ? 1 : 0);
    }

    head_kernel<<<(N_NODES + 3) / 4, 128>>>(bufB, hw1, hb1, hw2, hb2, out);
}